// round 1
// baseline (speedup 1.0000x reference)
#include <cuda_runtime.h>

#define NN 8192
#define DD 128

// scratch (allocation-free rule: device globals)
__device__ float g_dinv[NN];
__device__ float g_g[NN * DD];

// ---------------------------------------------------------------------------
// Kernel 1: dinv[i] = rsqrt(sum_j adj[i,j])  (0 if deg <= 0)
// one block per row, float4 loads
// ---------------------------------------------------------------------------
__global__ void deg_kernel(const float* __restrict__ adj) {
    int row = blockIdx.x;
    const float4* a = reinterpret_cast<const float4*>(adj + (size_t)row * NN);
    float s = 0.f;
    #pragma unroll 4
    for (int i = threadIdx.x; i < NN / 4; i += 256) {
        float4 v = a[i];
        s += (v.x + v.y) + (v.z + v.w);
    }
    __shared__ float red[256];
    red[threadIdx.x] = s;
    __syncthreads();
    #pragma unroll
    for (int off = 128; off > 0; off >>= 1) {
        if (threadIdx.x < off) red[threadIdx.x] += red[threadIdx.x + off];
        __syncthreads();
    }
    if (threadIdx.x == 0) {
        float d = red[0];
        g_dinv[row] = d > 0.f ? rsqrtf(d) : 0.f;
    }
}

// ---------------------------------------------------------------------------
// Kernel 2: g[j,:] = dinv[j] * (x[j,:] @ W)
// block = 128 threads (one per output col), 8 rows per block
// ---------------------------------------------------------------------------
__global__ void proj_kernel(const float* __restrict__ x,
                            const float* __restrict__ w) {
    const int ROWS = 8;
    __shared__ float xs[ROWS][DD];
    int r0 = blockIdx.x * ROWS;
    for (int i = threadIdx.x; i < ROWS * DD; i += 128)
        xs[i / DD][i % DD] = x[(size_t)r0 * DD + i];
    __syncthreads();

    int c = threadIdx.x;  // 0..127
    float acc[ROWS];
    #pragma unroll
    for (int r = 0; r < ROWS; r++) acc[r] = 0.f;

    for (int k = 0; k < DD; k++) {
        float wv = w[k * DD + c];
        #pragma unroll
        for (int r = 0; r < ROWS; r++) acc[r] += xs[r][k] * wv;
    }
    #pragma unroll
    for (int r = 0; r < ROWS; r++)
        g_g[(size_t)(r0 + r) * DD + c] = acc[r] * g_dinv[r0 + r];
}

// ---------------------------------------------------------------------------
// Kernel 3: out[i,:] = dinv[i] * (adj @ g)[i,:] + bias
// Tiled SGEMM: BM=64, BN=128 (full width), BK=16, 256 threads,
// thread tile 8 rows x 4 cols.
// ---------------------------------------------------------------------------
__global__ void __launch_bounds__(256, 2)
gemm_kernel(const float* __restrict__ A,        // adj [NN, NN]
            const float* __restrict__ bias,
            float* __restrict__ out) {
    const int BM = 64, BK = 16;
    __shared__ float As[BK][BM];     // A tile transposed
    __shared__ float Bs[BK][DD];

    int tid  = threadIdx.x;
    int brow = blockIdx.x * BM;

    int tx = tid % 32;   // col group: cols tx*4 .. tx*4+3
    int ty = tid / 32;   // row group: rows ty*8 .. ty*8+7

    // load-index mapping
    int a_r  = tid / 4;  // 0..63 (A row within tile)
    int a_c4 = tid % 4;  // which float4 of the 16 K-cols
    int b_r  = tid / 32; // 0..7  (loads rows b_r and b_r+8)
    int b_c4 = tid % 32; // float4 col within 128

    float acc[8][4];
    #pragma unroll
    for (int r = 0; r < 8; r++)
        #pragma unroll
        for (int c = 0; c < 4; c++) acc[r][c] = 0.f;

    for (int k0 = 0; k0 < NN; k0 += BK) {
        // A tile: 64 x 16, store transposed
        float4 av = *reinterpret_cast<const float4*>(
            A + (size_t)(brow + a_r) * NN + k0 + a_c4 * 4);
        As[a_c4 * 4 + 0][a_r] = av.x;
        As[a_c4 * 4 + 1][a_r] = av.y;
        As[a_c4 * 4 + 2][a_r] = av.z;
        As[a_c4 * 4 + 3][a_r] = av.w;

        // B tile: 16 x 128 from g (L2-resident)
        #pragma unroll
        for (int i = 0; i < 2; i++) {
            int kr = b_r + i * 8;
            float4 bv = *reinterpret_cast<const float4*>(
                g_g + (size_t)(k0 + kr) * DD + b_c4 * 4);
            *reinterpret_cast<float4*>(&Bs[kr][b_c4 * 4]) = bv;
        }
        __syncthreads();

        #pragma unroll
        for (int k = 0; k < BK; k++) {
            float ar[8];
            float4 a0 = *reinterpret_cast<float4*>(&As[k][ty * 8]);
            float4 a1 = *reinterpret_cast<float4*>(&As[k][ty * 8 + 4]);
            ar[0] = a0.x; ar[1] = a0.y; ar[2] = a0.z; ar[3] = a0.w;
            ar[4] = a1.x; ar[5] = a1.y; ar[6] = a1.z; ar[7] = a1.w;
            float4 bv = *reinterpret_cast<float4*>(&Bs[k][tx * 4]);
            float br4[4] = {bv.x, bv.y, bv.z, bv.w};
            #pragma unroll
            for (int r = 0; r < 8; r++)
                #pragma unroll
                for (int c = 0; c < 4; c++)
                    acc[r][c] += ar[r] * br4[c];
        }
        __syncthreads();
    }

    // epilogue: scale by dinv[row], add bias
    float b0 = bias[tx * 4 + 0];
    float b1 = bias[tx * 4 + 1];
    float b2 = bias[tx * 4 + 2];
    float b3 = bias[tx * 4 + 3];
    #pragma unroll
    for (int r = 0; r < 8; r++) {
        int gr = brow + ty * 8 + r;
        float dv = g_dinv[gr];
        float4 o;
        o.x = acc[r][0] * dv + b0;
        o.y = acc[r][1] * dv + b1;
        o.z = acc[r][2] * dv + b2;
        o.w = acc[r][3] * dv + b3;
        *reinterpret_cast<float4*>(out + (size_t)gr * DD + tx * 4) = o;
    }
}

extern "C" void kernel_launch(void* const* d_in, const int* in_sizes, int n_in,
                              void* d_out, int out_size) {
    const float* x    = (const float*)d_in[0];   // [8192,128]
    const float* adj  = (const float*)d_in[1];   // [8192,8192]
    const float* w    = (const float*)d_in[2];   // [128,128]
    const float* bias = (const float*)d_in[3];   // [128]
    float* out = (float*)d_out;

    deg_kernel<<<NN, 256>>>(adj);
    proj_kernel<<<NN / 8, 128>>>(x, w);
    gemm_kernel<<<NN / 64, 256>>>(adj, bias, out);
}

// round 6
// speedup vs baseline: 3.8985x; 3.8985x over previous
#include <cuda_runtime.h>
#include <cstdint>
#include <cstddef>

#define NN 8192
#define DD 128
#define BM 64
#define BK 32
#define STAGES 4
#define NTILE (NN / BK)                 // 256
#define THREADS 128
#define STAGE_FLOATS (BM * BK + BK * DD)   // 2048 + 4096 = 6144
#define SMEM_BYTES (STAGES * STAGE_FLOATS * 4)   // 98304

// scratch (allocation-free rule: device globals)
__device__ float g_dinv[NN];
__device__ float g_g[NN * DD];          // tf32-rounded dinv[k] * (x@W), natural [k][n]

// ---------------------------------------------------------------------------
// helpers
// ---------------------------------------------------------------------------
__device__ __forceinline__ uint32_t smem_u32(const void* p) {
    uint32_t a;
    asm("{ .reg .u64 t; cvta.to.shared.u64 t, %1; cvt.u32.u64 %0, t; }" : "=r"(a) : "l"(p));
    return a;
}
__device__ __forceinline__ void cp16(uint32_t dst, const void* src) {
    asm volatile("cp.async.cg.shared.global [%0], [%1], 16;" :: "r"(dst), "l"(src));
}
#define CP_COMMIT() asm volatile("cp.async.commit_group;" ::: "memory")
template <int N>
__device__ __forceinline__ void cp_wait() {
    asm volatile("cp.async.wait_group %0;" :: "n"(N) : "memory");
}
__device__ __forceinline__ uint32_t f2tf32(float f) {
    uint32_t u;
    asm("cvt.rn.tf32.f32 %0, %1;" : "=r"(u) : "f"(f));
    return u;
}

// ---------------------------------------------------------------------------
// Kernel 1: dinv[i] = rsqrt(sum_j adj[i,j])   (0 if deg <= 0)
// ---------------------------------------------------------------------------
__global__ void deg_kernel(const float* __restrict__ adj) {
    int row = blockIdx.x;
    const float4* a = reinterpret_cast<const float4*>(adj + (size_t)row * NN);
    float s = 0.f;
    #pragma unroll 4
    for (int i = threadIdx.x; i < NN / 4; i += 256) {
        float4 v = a[i];
        s += (v.x + v.y) + (v.z + v.w);
    }
    __shared__ float red[256];
    red[threadIdx.x] = s;
    __syncthreads();
    #pragma unroll
    for (int off = 128; off > 0; off >>= 1) {
        if (threadIdx.x < off) red[threadIdx.x] += red[threadIdx.x + off];
        __syncthreads();
    }
    if (threadIdx.x == 0) {
        float d = red[0];
        g_dinv[row] = d > 0.f ? rsqrtf(d) : 0.f;
    }
}

// ---------------------------------------------------------------------------
// Kernel 2: g[k][n] = round_tf32( dinv[k] * (x[k,:] @ W)[n] )
// ---------------------------------------------------------------------------
__global__ void proj_kernel(const float* __restrict__ x,
                            const float* __restrict__ w) {
    const int ROWS = 8;
    __shared__ float xs[ROWS][DD];
    int r0 = blockIdx.x * ROWS;
    for (int i = threadIdx.x; i < ROWS * DD; i += 128)
        xs[i / DD][i % DD] = x[(size_t)r0 * DD + i];
    __syncthreads();

    int c = threadIdx.x;
    float acc[ROWS];
    #pragma unroll
    for (int r = 0; r < ROWS; r++) acc[r] = 0.f;

    for (int k = 0; k < DD; k++) {
        float wv = w[k * DD + c];
        #pragma unroll
        for (int r = 0; r < ROWS; r++) acc[r] += xs[r][k] * wv;
    }
    #pragma unroll
    for (int r = 0; r < ROWS; r++) {
        float v = acc[r] * g_dinv[r0 + r];
        g_g[(size_t)(r0 + r) * DD + c] = __uint_as_float(f2tf32(v));
    }
}

// ---------------------------------------------------------------------------
// Kernel 3: out = dinv * (adj @ g) + bias via mma.sync tf32 (m16n8k8)
// 128 CTAs (M tile 64, full N=128), 4 warps, warp tile 64x32, BK=32, 4 stages.
// A smem swizzle: word = m*32 + (k ^ ((m&7)<<2))     -> conflict-free frags
// B smem swizzle: word = k*128 + 4*((n/4) ^ ((k&3)<<1)) + (n&3)
// ---------------------------------------------------------------------------
__global__ void __launch_bounds__(THREADS, 1)
gemm_kernel(const float* __restrict__ adj,
            const float* __restrict__ bias,
            float* __restrict__ out) {
    extern __shared__ float sm[];
    const uint32_t sb = smem_u32(sm);
    const int tid = threadIdx.x;
    const int wid = tid >> 5, lane = tid & 31;
    const int rq = lane >> 2, c0 = lane & 3;
    const int m0 = blockIdx.x * BM;

    float c[4][4][4];
    #pragma unroll
    for (int i = 0; i < 4; i++)
        #pragma unroll
        for (int j = 0; j < 4; j++)
            #pragma unroll
            for (int k = 0; k < 4; k++) c[i][j][k] = 0.f;

    auto load_tile = [&](int s, int kt) {
        int k0 = kt * BK;
        uint32_t sA = sb + s * (STAGE_FLOATS * 4);
        uint32_t sB = sA + BM * BK * 4;
        #pragma unroll
        for (int i = 0; i < 4; i++) {                 // A: 64x32 = 512 chunks
            int cid = tid + i * THREADS;
            int m = cid >> 3, t = cid & 7;
            cp16(sA + (uint32_t)(m * BK + 4 * (t ^ (m & 7))) * 4,
                 adj + (size_t)(m0 + m) * NN + k0 + t * 4);
        }
        #pragma unroll
        for (int i = 0; i < 8; i++) {                 // B: 32x128 = 1024 chunks
            int cid = tid + i * THREADS;
            int k = cid >> 5, t = cid & 31;
            cp16(sB + (uint32_t)(k * DD + 4 * (t ^ ((k & 3) << 1))) * 4,
                 g_g + (size_t)(k0 + k) * DD + t * 4);
        }
        CP_COMMIT();
    };

    auto compute_tile = [&](int s) {
        const float* As = sm + s * STAGE_FLOATS;
        const float* Bs = As + BM * BK;
        #pragma unroll
        for (int ks = 0; ks < 4; ks++) {
            // A fragments: a0=(r,c) a1=(r+8,c) a2=(r,c+4) a3=(r+8,c+4)
            uint32_t a[4][4];
            #pragma unroll
            for (int mf = 0; mf < 4; mf++) {
                int r = mf * 16 + rq;
                int w0 = r * BK + ((ks * 8 + c0) ^ (rq << 2));
                a[mf][0] = f2tf32(As[w0]);
                a[mf][1] = f2tf32(As[w0 + 8 * BK]);
                a[mf][2] = f2tf32(As[w0 ^ 4]);
                a[mf][3] = f2tf32(As[(w0 + 8 * BK) ^ 4]);
            }
            // B fragments: b0=B[k=c0][n], b1=B[k=c0+4][n]  (already tf32)
            uint32_t b[4][2];
            #pragma unroll
            for (int nf = 0; nf < 4; nf++) {
                int n = wid * 32 + nf * 8 + rq;
                int w = (ks * 8 + c0) * DD + (n ^ (c0 << 3));
                b[nf][0] = __float_as_uint(Bs[w]);
                b[nf][1] = __float_as_uint(Bs[w + 4 * DD]);
            }
            #pragma unroll
            for (int mf = 0; mf < 4; mf++)
                #pragma unroll
                for (int nf = 0; nf < 4; nf++)
                    asm volatile(
                        "mma.sync.aligned.m16n8k8.row.col.f32.tf32.tf32.f32 "
                        "{%0,%1,%2,%3}, {%4,%5,%6,%7}, {%8,%9}, {%0,%1,%2,%3};"
                        : "+f"(c[mf][nf][0]), "+f"(c[mf][nf][1]),
                          "+f"(c[mf][nf][2]), "+f"(c[mf][nf][3])
                        : "r"(a[mf][0]), "r"(a[mf][1]), "r"(a[mf][2]), "r"(a[mf][3]),
                          "r"(b[nf][0]), "r"(b[nf][1]));
        }
    };

    load_tile(0, 0);
    load_tile(1, 1);
    load_tile(2, 2);

    #pragma unroll 1
    for (int it = 0; it < NTILE - 2; it++) {
        cp_wait<2>();
        __syncthreads();
        if (it < NTILE - 3) load_tile((it + 3) & 3, it + 3);
        compute_tile(it & 3);
    }
    cp_wait<1>(); __syncthreads(); compute_tile((NTILE - 2) & 3);
    cp_wait<0>(); __syncthreads(); compute_tile((NTILE - 1) & 3);

    // epilogue: scale rows by dinv, add bias
    #pragma unroll
    for (int mf = 0; mf < 4; mf++) {
        int r = m0 + mf * 16 + rq;
        float dv0 = g_dinv[r], dv1 = g_dinv[r + 8];
        #pragma unroll
        for (int nf = 0; nf < 4; nf++) {
            int n = wid * 32 + nf * 8 + c0 * 2;
            float bx = bias[n], by = bias[n + 1];
            float2 o0 = { c[mf][nf][0] * dv0 + bx, c[mf][nf][1] * dv0 + by };
            float2 o1 = { c[mf][nf][2] * dv1 + bx, c[mf][nf][3] * dv1 + by };
            *reinterpret_cast<float2*>(out + (size_t)r * DD + n) = o0;
            *reinterpret_cast<float2*>(out + (size_t)(r + 8) * DD + n) = o1;
        }
    }
}

// ---------------------------------------------------------------------------
// Host
// ---------------------------------------------------------------------------
extern "C" void kernel_launch(void* const* d_in, const int* in_sizes, int n_in,
                              void* d_out, int out_size) {
    const float* x    = (const float*)d_in[0];   // [8192,128]
    const float* adj  = (const float*)d_in[1];   // [8192,8192]
    const float* w    = (const float*)d_in[2];   // [128,128]
    const float* bias = (const float*)d_in[3];   // [128]
    float* out = (float*)d_out;

    deg_kernel<<<NN, 256>>>(adj);
    proj_kernel<<<NN / 8, 128>>>(x, w);

    cudaFuncSetAttribute(gemm_kernel, cudaFuncAttributeMaxDynamicSharedMemorySize, SMEM_BYTES);
    gemm_kernel<<<NN / BM, THREADS, SMEM_BYTES>>>(adj, bias, out);
}

// round 7
// speedup vs baseline: 4.3226x; 1.1088x over previous
#include <cuda_runtime.h>
#include <cstdint>
#include <cstddef>

#define NN 8192
#define DD 128
#define BM 64
#define BK 32
#define NTILE (NN / BK)                 // 256
#define NT2 (NTILE / 2)                 // 128 tiles per k-group
#define THREADS 256
#define GSTAGES 4
#define STAGE_FLOATS (BM * BK + BK * DD)       // 6144
#define STAGE_BYTES (STAGE_FLOATS * 4)         // 24576
#define GROUP_BYTES (GSTAGES * STAGE_BYTES)    // 98304
#define SMEM_BYTES (2 * GROUP_BYTES)           // 196608

// scratch (allocation-free rule: device globals)
__device__ float g_dinv[NN];
__device__ float g_g[NN * DD];          // tf32-rounded dinv[k] * (x@W), natural [k][n]

// ---------------------------------------------------------------------------
// helpers
// ---------------------------------------------------------------------------
__device__ __forceinline__ uint32_t smem_u32(const void* p) {
    uint32_t a;
    asm("{ .reg .u64 t; cvta.to.shared.u64 t, %1; cvt.u32.u64 %0, t; }" : "=r"(a) : "l"(p));
    return a;
}
__device__ __forceinline__ void cp16(uint32_t dst, const void* src) {
    asm volatile("cp.async.cg.shared.global [%0], [%1], 16;" :: "r"(dst), "l"(src));
}
#define CP_COMMIT() asm volatile("cp.async.commit_group;" ::: "memory")
template <int N>
__device__ __forceinline__ void cp_wait() {
    asm volatile("cp.async.wait_group %0;" :: "n"(N) : "memory");
}
__device__ __forceinline__ void bar_g(int id) {
    asm volatile("bar.sync %0, %1;" :: "r"(id), "r"(128) : "memory");
}
__device__ __forceinline__ uint32_t f2tf32(float f) {
    uint32_t u;
    asm("cvt.rn.tf32.f32 %0, %1;" : "=r"(u) : "f"(f));
    return u;
}

// ---------------------------------------------------------------------------
// Kernel 1: dinv[i] = rsqrt(sum_j adj[i,j])   (0 if deg <= 0)
// ---------------------------------------------------------------------------
__global__ void deg_kernel(const float* __restrict__ adj) {
    int row = blockIdx.x;
    const float4* a = reinterpret_cast<const float4*>(adj + (size_t)row * NN);
    float s = 0.f;
    #pragma unroll 4
    for (int i = threadIdx.x; i < NN / 4; i += 256) {
        float4 v = a[i];
        s += (v.x + v.y) + (v.z + v.w);
    }
    __shared__ float red[256];
    red[threadIdx.x] = s;
    __syncthreads();
    #pragma unroll
    for (int off = 128; off > 0; off >>= 1) {
        if (threadIdx.x < off) red[threadIdx.x] += red[threadIdx.x + off];
        __syncthreads();
    }
    if (threadIdx.x == 0) {
        float d = red[0];
        g_dinv[row] = d > 0.f ? rsqrtf(d) : 0.f;
    }
}

// ---------------------------------------------------------------------------
// Kernel 2: g[k][n] = round_tf32( dinv[k] * (x[k,:] @ W)[n] )
// ---------------------------------------------------------------------------
__global__ void proj_kernel(const float* __restrict__ x,
                            const float* __restrict__ w) {
    const int ROWS = 8;
    __shared__ float xs[ROWS][DD];
    int r0 = blockIdx.x * ROWS;
    for (int i = threadIdx.x; i < ROWS * DD; i += 128)
        xs[i / DD][i % DD] = x[(size_t)r0 * DD + i];
    __syncthreads();

    int c = threadIdx.x;
    float acc[ROWS];
    #pragma unroll
    for (int r = 0; r < ROWS; r++) acc[r] = 0.f;

    for (int k = 0; k < DD; k++) {
        float wv = w[k * DD + c];
        #pragma unroll
        for (int r = 0; r < ROWS; r++) acc[r] += xs[r][k] * wv;
    }
    #pragma unroll
    for (int r = 0; r < ROWS; r++) {
        float v = acc[r] * g_dinv[r0 + r];
        g_g[(size_t)(r0 + r) * DD + c] = __uint_as_float(f2tf32(v));
    }
}

// ---------------------------------------------------------------------------
// Kernel 3: split-K tf32 mma.sync GEMM.
// 128 CTAs, 256 threads = 2 warp-groups of 4 warps.
// Group g processes k-tiles kt = 2t+g with a private 4-stage pipeline and
// named barrier (1+g). Combine via smem, epilogue by group 0.
// ---------------------------------------------------------------------------
__global__ void __launch_bounds__(THREADS, 1)
gemm_kernel(const float* __restrict__ adj,
            const float* __restrict__ bias,
            float* __restrict__ out) {
    extern __shared__ float sm[];
    const uint32_t sb = smem_u32(sm);
    const int tid = threadIdx.x;
    const int wid = tid >> 5, lane = tid & 31;
    const int wg = wid >> 2;            // warp-group (0/1)
    const int wl = wid & 3;             // warp within group
    const int tid_g = tid & 127;        // thread within group
    const int rq = lane >> 2, c0 = lane & 3;
    const int m0 = blockIdx.x * BM;

    const uint32_t gbase = sb + wg * GROUP_BYTES;
    float* gbase_f = sm + wg * (GROUP_BYTES / 4);

    float c[4][4][4];
    #pragma unroll
    for (int i = 0; i < 4; i++)
        #pragma unroll
        for (int j = 0; j < 4; j++)
            #pragma unroll
            for (int k = 0; k < 4; k++) c[i][j][k] = 0.f;

    auto load_tile = [&](int s, int t) {
        int k0 = (2 * t + wg) * BK;
        uint32_t sA = gbase + s * STAGE_BYTES;
        uint32_t sB = sA + BM * BK * 4;
        #pragma unroll
        for (int i = 0; i < 4; i++) {                 // A: 64x32 = 512 chunks / 128 thr
            int cid = tid_g + i * 128;
            int m = cid >> 3, tt = cid & 7;
            cp16(sA + (uint32_t)(m * BK + 4 * (tt ^ (m & 7))) * 4,
                 adj + (size_t)(m0 + m) * NN + k0 + tt * 4);
        }
        #pragma unroll
        for (int i = 0; i < 8; i++) {                 // B: 32x128 = 1024 chunks / 128 thr
            int cid = tid_g + i * 128;
            int k = cid >> 5, tt = cid & 31;
            cp16(sB + (uint32_t)(k * DD + 4 * (tt ^ ((k & 3) << 1))) * 4,
                 g_g + (size_t)(k0 + k) * DD + tt * 4);
        }
        CP_COMMIT();
    };

    auto compute_tile = [&](int s) {
        const float* As = gbase_f + s * STAGE_FLOATS;
        const float* Bs = As + BM * BK;
        #pragma unroll
        for (int ks = 0; ks < 4; ks++) {
            uint32_t a[4][4];
            #pragma unroll
            for (int mf = 0; mf < 4; mf++) {
                int r = mf * 16 + rq;
                int w0 = r * BK + ((ks * 8 + c0) ^ (rq << 2));
                a[mf][0] = f2tf32(As[w0]);
                a[mf][1] = f2tf32(As[w0 + 8 * BK]);
                a[mf][2] = f2tf32(As[w0 ^ 4]);
                a[mf][3] = f2tf32(As[(w0 + 8 * BK) ^ 4]);
            }
            uint32_t b[4][2];
            #pragma unroll
            for (int nf = 0; nf < 4; nf++) {
                int n = wl * 32 + nf * 8 + rq;
                int w = (ks * 8 + c0) * DD + (n ^ (c0 << 3));
                b[nf][0] = __float_as_uint(Bs[w]);
                b[nf][1] = __float_as_uint(Bs[w + 4 * DD]);
            }
            #pragma unroll
            for (int mf = 0; mf < 4; mf++)
                #pragma unroll
                for (int nf = 0; nf < 4; nf++)
                    asm volatile(
                        "mma.sync.aligned.m16n8k8.row.col.f32.tf32.tf32.f32 "
                        "{%0,%1,%2,%3}, {%4,%5,%6,%7}, {%8,%9}, {%0,%1,%2,%3};"
                        : "+f"(c[mf][nf][0]), "+f"(c[mf][nf][1]),
                          "+f"(c[mf][nf][2]), "+f"(c[mf][nf][3])
                        : "r"(a[mf][0]), "r"(a[mf][1]), "r"(a[mf][2]), "r"(a[mf][3]),
                          "r"(b[nf][0]), "r"(b[nf][1]));
        }
    };

    load_tile(0, 0);
    load_tile(1, 1);
    load_tile(2, 2);

    #pragma unroll 1
    for (int t = 0; t < NT2 - 2; t++) {
        cp_wait<2>();
        bar_g(1 + wg);
        if (t < NT2 - 3) load_tile((t + 3) & 3, t + 3);
        compute_tile(t & 3);
    }
    cp_wait<1>(); bar_g(1 + wg); compute_tile((NT2 - 2) & 3);
    cp_wait<0>(); bar_g(1 + wg); compute_tile((NT2 - 1) & 3);

    // ---- combine: group 1 -> smem, group 0 adds ----
    __syncthreads();
    float4* cbuf = reinterpret_cast<float4*>(sm);
    if (wg == 1) {
        #pragma unroll
        for (int mf = 0; mf < 4; mf++)
            #pragma unroll
            for (int nf = 0; nf < 4; nf++) {
                float4 v = { c[mf][nf][0], c[mf][nf][1], c[mf][nf][2], c[mf][nf][3] };
                cbuf[(mf * 4 + nf) * 128 + tid_g] = v;
            }
    }
    __syncthreads();
    if (wg == 0) {
        #pragma unroll
        for (int mf = 0; mf < 4; mf++) {
            int r = m0 + mf * 16 + rq;
            float dv0 = g_dinv[r], dv1 = g_dinv[r + 8];
            #pragma unroll
            for (int nf = 0; nf < 4; nf++) {
                float4 p = cbuf[(mf * 4 + nf) * 128 + tid_g];
                int n = wl * 32 + nf * 8 + c0 * 2;
                float bx = bias[n], by = bias[n + 1];
                float2 o0 = { (c[mf][nf][0] + p.x) * dv0 + bx,
                              (c[mf][nf][1] + p.y) * dv0 + by };
                float2 o1 = { (c[mf][nf][2] + p.z) * dv1 + bx,
                              (c[mf][nf][3] + p.w) * dv1 + by };
                *reinterpret_cast<float2*>(out + (size_t)r * DD + n) = o0;
                *reinterpret_cast<float2*>(out + (size_t)(r + 8) * DD + n) = o1;
            }
        }
    }
}

// ---------------------------------------------------------------------------
// Host
// ---------------------------------------------------------------------------
extern "C" void kernel_launch(void* const* d_in, const int* in_sizes, int n_in,
                              void* d_out, int out_size) {
    const float* x    = (const float*)d_in[0];   // [8192,128]
    const float* adj  = (const float*)d_in[1];   // [8192,8192]
    const float* w    = (const float*)d_in[2];   // [128,128]
    const float* bias = (const float*)d_in[3];   // [128]
    float* out = (float*)d_out;

    deg_kernel<<<NN, 256>>>(adj);
    proj_kernel<<<NN / 8, 128>>>(x, w);

    cudaFuncSetAttribute(gemm_kernel, cudaFuncAttributeMaxDynamicSharedMemorySize, SMEM_BYTES);
    gemm_kernel<<<NN / BM, THREADS, SMEM_BYTES>>>(adj, bias, out);
}